// round 4
// baseline (speedup 1.0000x reference)
#include <cuda_runtime.h>
#include <cuda_fp16.h>
#include <cuda_bf16.h>

// Problem constants
#define BB 8
#define CC 32
#define TT 12
#define NNODE 5000
#define EDGES 80000
#define FF (BB*TT*CC)   // 3072 features per node
#define BT (BB*TT)      // 96
#define YU4 (FF/8)      // 384 uint4 (half8) per node

// ---------------------------------------------------------------------------
// Scratch (static __device__ arrays — no allocations allowed)
// ---------------------------------------------------------------------------
__device__ __half g_y  [(size_t)NNODE * FF];   // y = norm_src*(xW), node-major [n][bt][c], fp16
__device__ __half g_agg[(size_t)NNODE * FF];   // aggregated, node-major, fp16
__device__ int    g_ptr    [NNODE + 1];        // CSR row ptr by dst
__device__ int    g_csr_src[EDGES];            // src per edge, bucketed by dst
__device__ float  g_norm_src[NNODE];
__device__ float  g_norm_dst[NNODE];

// ---------------------------------------------------------------------------
// K_prep: single block does degree histograms (smem atomics), norms,
// warp-shuffle exclusive scan, and deterministic-enough CSR scatter.
// Replaces 5 kernels (~22us) with one (~7us).
// ---------------------------------------------------------------------------
__global__ __launch_bounds__(1024, 1)
void k_prep(const int* __restrict__ src, const int* __restrict__ dst) {
    __shared__ int s_in [NNODE];   // deg_in, then reused as exclusive ptr
    __shared__ int s_out[NNODE];   // deg_out, then reused as scatter cursor
    __shared__ int s_wsum[32];

    const int tid  = threadIdx.x;
    const int lane = tid & 31;
    const int warp = tid >> 5;

    for (int i = tid; i < NNODE; i += 1024) { s_in[i] = 0; s_out[i] = 0; }
    __syncthreads();

    for (int e = tid; e < EDGES; e += 1024) {
        atomicAdd(&s_out[src[e]], 1);
        atomicAdd(&s_in [dst[e]], 1);
    }
    __syncthreads();

    // norms
    for (int i = tid; i < NNODE; i += 1024) {
        g_norm_src[i] = rsqrtf((float)max(s_out[i], 1));
        g_norm_dst[i] = rsqrtf((float)max(s_in [i], 1));
    }

    // exclusive scan of s_in -> g_ptr (5 elems/thread, warp shuffles)
    const int base = tid * 5;
    int v[5];
    int tsum = 0;
    #pragma unroll
    for (int k = 0; k < 5; k++) {
        v[k] = (base + k < NNODE) ? s_in[base + k] : 0;
        tsum += v[k];
    }
    int incl = tsum;
    #pragma unroll
    for (int off = 1; off < 32; off <<= 1) {
        int t = __shfl_up_sync(0xffffffffu, incl, off);
        if (lane >= off) incl += t;
    }
    if (lane == 31) s_wsum[warp] = incl;
    __syncthreads();
    if (warp == 0) {
        int w = s_wsum[lane];
        int wi = w;
        #pragma unroll
        for (int off = 1; off < 32; off <<= 1) {
            int t = __shfl_up_sync(0xffffffffu, wi, off);
            if (lane >= off) wi += t;
        }
        s_wsum[lane] = wi - w;   // exclusive warp offsets
    }
    __syncthreads();

    int run = s_wsum[warp] + incl - tsum;   // exclusive prefix at base
    #pragma unroll
    for (int k = 0; k < 5; k++) {
        if (base + k < NNODE) {
            g_ptr[base + k] = run;
            s_in [base + k] = run;          // reuse as smem ptr table
            run += v[k];
        }
    }
    if (tid == 0) g_ptr[NNODE] = EDGES;

    // reuse s_out as cursor
    for (int i = tid; i < NNODE; i += 1024) s_out[i] = 0;
    __syncthreads();

    for (int e = tid; e < EDGES; e += 1024) {
        int d = dst[e];
        int pos = s_in[d] + atomicAdd(&s_out[d], 1);
        g_csr_src[pos] = src[e];
    }
}

// ---------------------------------------------------------------------------
// K_y: y[n][bt][c'] = norm_src[n] * sum_c x[b,c,t,n] * W[c][c']  (fp16 out)
// x loads coalesced over n; y stored node-major via uint4 (8 halves).
// ---------------------------------------------------------------------------
__global__ void k_y(const float* __restrict__ x, const float* __restrict__ W) {
    __shared__ float Ws[CC * CC];
    int tid = threadIdx.y * 32 + threadIdx.x;
    for (int i = tid; i < CC * CC; i += 256) Ws[i] = W[i];
    __syncthreads();

    int n  = blockIdx.x * 32 + threadIdx.x;
    int bt = blockIdx.y * 8 + threadIdx.y;
    if (n >= NNODE) return;
    int b = bt / TT, t = bt - b * TT;

    // x index: ((b*CC + c)*TT + t)*NNODE + n
    const float* xp = x + ((size_t)b * CC * TT) * NNODE + (size_t)t * NNODE + n;
    float xa[CC];
    #pragma unroll
    for (int c = 0; c < CC; c++) xa[c] = xp[(size_t)c * TT * NNODE];

    float ns = g_norm_src[n];
    uint4* yp = reinterpret_cast<uint4*>(g_y + (size_t)n * FF + (size_t)bt * CC);
    #pragma unroll
    for (int c8 = 0; c8 < CC / 8; c8++) {
        float acc[8];
        #pragma unroll
        for (int j = 0; j < 8; j++) acc[j] = 0.f;
        #pragma unroll
        for (int c = 0; c < CC; c++) {
            float xv = xa[c];
            const float* wr = &Ws[c * CC + c8 * 8];
            #pragma unroll
            for (int j = 0; j < 8; j++) acc[j] += xv * wr[j];
        }
        __half2 h[4];
        #pragma unroll
        for (int j = 0; j < 4; j++)
            h[j] = __floats2half2_rn(acc[2*j] * ns, acc[2*j+1] * ns);
        uint4 pack;
        pack.x = *reinterpret_cast<unsigned*>(&h[0]);
        pack.y = *reinterpret_cast<unsigned*>(&h[1]);
        pack.z = *reinterpret_cast<unsigned*>(&h[2]);
        pack.w = *reinterpret_cast<unsigned*>(&h[3]);
        yp[c8] = pack;
    }
}

// ---------------------------------------------------------------------------
// K_agg: agg[d] = norm_dst[d] * sum_{e in CSR[d]} y[src[e]]
// One block per dst node, 128 threads, 3 uint4 (24 halves) per thread.
// fp16 gather (6KB/node, mostly L2-hit), fp32 accumulate, fp16 store.
// ---------------------------------------------------------------------------
__global__ __launch_bounds__(128)
void k_agg() {
    int d = blockIdx.x;
    int tid = threadIdx.x;
    int beg = g_ptr[d], end = g_ptr[d + 1];

    float2 acc[12];
    #pragma unroll
    for (int j = 0; j < 12; j++) acc[j] = make_float2(0.f, 0.f);

    __shared__ int ss[128];
    for (int base = beg; base < end; base += 128) {
        int m = min(128, end - base);
        if (tid < m) ss[tid] = g_csr_src[base + tid];
        __syncthreads();
        #pragma unroll 4
        for (int i = 0; i < m; i++) {
            const uint4* ys = reinterpret_cast<const uint4*>(g_y + (size_t)ss[i] * FF);
            uint4 v0 = ys[tid];
            uint4 v1 = ys[tid + 128];
            uint4 v2 = ys[tid + 256];
            const unsigned* u = &v0.x;
            #pragma unroll
            for (int j = 0; j < 4; j++) {
                float2 f = __half22float2(*reinterpret_cast<const __half2*>(&u[j]));
                acc[j].x += f.x; acc[j].y += f.y;
            }
            u = &v1.x;
            #pragma unroll
            for (int j = 0; j < 4; j++) {
                float2 f = __half22float2(*reinterpret_cast<const __half2*>(&u[j]));
                acc[4+j].x += f.x; acc[4+j].y += f.y;
            }
            u = &v2.x;
            #pragma unroll
            for (int j = 0; j < 4; j++) {
                float2 f = __half22float2(*reinterpret_cast<const __half2*>(&u[j]));
                acc[8+j].x += f.x; acc[8+j].y += f.y;
            }
        }
        __syncthreads();
    }

    float nd = g_norm_dst[d];
    uint4* ap = reinterpret_cast<uint4*>(g_agg + (size_t)d * FF);
    #pragma unroll
    for (int g = 0; g < 3; g++) {
        __half2 h[4];
        #pragma unroll
        for (int j = 0; j < 4; j++)
            h[j] = __floats2half2_rn(acc[4*g+j].x * nd, acc[4*g+j].y * nd);
        uint4 pack;
        pack.x = *reinterpret_cast<unsigned*>(&h[0]);
        pack.y = *reinterpret_cast<unsigned*>(&h[1]);
        pack.z = *reinterpret_cast<unsigned*>(&h[2]);
        pack.w = *reinterpret_cast<unsigned*>(&h[3]);
        ap[tid + g * 128] = pack;
    }
}

// ---------------------------------------------------------------------------
// K_out: out[b,c,t,n] = relu(x[b,c,t,n] + bias[c] + agg[n][b][t][c])
// smem 32x32 tile transpose: agg read coalesced over c, out/x coalesced over n.
// ---------------------------------------------------------------------------
__global__ void k_out(const float* __restrict__ x, const float* __restrict__ bias,
                      float* __restrict__ out) {
    __shared__ float s[32][33];
    int bt = blockIdx.y;
    int b = bt / TT, t = bt - b * TT;
    int n0 = blockIdx.x * 32;

    #pragma unroll
    for (int k = 0; k < 4; k++) {
        int nl = threadIdx.y + k * 8;
        int n = n0 + nl;
        if (n < NNODE)
            s[nl][threadIdx.x] =
                __half2float(g_agg[(size_t)n * FF + (size_t)bt * CC + threadIdx.x]);
    }
    __syncthreads();

    int n = n0 + threadIdx.x;
    if (n < NNODE) {
        #pragma unroll
        for (int k = 0; k < 4; k++) {
            int c = threadIdx.y + k * 8;
            size_t idx = (((size_t)b * CC + c) * TT + t) * NNODE + n;
            float v = x[idx] + bias[c] + s[threadIdx.x][c];
            out[idx] = fmaxf(v, 0.0f);
        }
    }
}

// ---------------------------------------------------------------------------
// Launch
// ---------------------------------------------------------------------------
extern "C" void kernel_launch(void* const* d_in, const int* in_sizes, int n_in,
                              void* d_out, int out_size) {
    const float* x    = (const float*)d_in[0];  // [B, C, T, N]
    const float* W    = (const float*)d_in[1];  // [C, C]
    const float* bias = (const float*)d_in[2];  // [C]
    const int*   src  = (const int*)d_in[3];    // [E]
    const int*   dst  = (const int*)d_in[4];    // [E]
    float*       out  = (float*)d_out;          // [B, C, T, N]

    k_prep<<<1, 1024>>>(src, dst);

    dim3 by((NNODE + 31) / 32, BT / 8);
    k_y<<<by, dim3(32, 8)>>>(x, W);

    k_agg<<<NNODE, 128>>>();

    k_out<<<dim3((NNODE + 31) / 32, BT), dim3(32, 8)>>>(x, bias, out);
}